// round 14
// baseline (speedup 1.0000x reference)
#include <cuda_runtime.h>
#include <cuda_fp16.h>
#include <cstdint>
#include <math.h>

#define DEV_INLINE __device__ __forceinline__

// Problem dims (fixed by the dataset)
constexpr int B_ = 128, T_ = 512, F_ = 512, M_ = 512;
constexpr float LN_EPS = 1e-5f;

// GEMM tiling (R12-verified 122.9us): CTA 128x128x64; 8 warps of 32x64; fp16 mma k16, f32 acc
constexpr int BM = 128, BN = 128, BK = 64;
constexpr int NKC = T_ / BK;     // 8 k-chunks
constexpr int THREADS = 256;
constexpr int NSTAGE = 3;

constexpr int A_STAGE_B = BM * BK * 2;            // 16384 B
constexpr int B_STAGE_B = BN * BK * 2;            // 16384 B
constexpr int STAGE_B   = A_STAGE_B + B_STAGE_B;  // 32 KB
constexpr int SMEM_BYTES = NSTAGE * STAGE_B;      // 96 KB

// Prep kernel dynamic smem layout (bytes)
constexpr int SX_STRIDE = 136;                     // halfs per row (8B-aligned rows)
constexpr int OFF_SX   = 0;                        // __half [512][136] = 139264
constexpr int OFF_RED  = 139264;                   // float [2][8][128] = 8192
constexpr int OFF_MURS = 147456;                   // float [2][128]   = 1024
constexpr int OFF_GB   = 148480;                   // float [2][512]   = 4096
constexpr int PREP_SMEM = 152576;

// Device scratch (no allocation allowed)
__device__ uint4 g_WfragH[32 * 16 * 2 * 32];           // 512KB: [m16][kc32][kstep2][lane]
__device__ uint4 g_BfragH[(size_t)B_ * 4 * 16 * 512];  // 64MB: [b][ft][kc32][np][kstep2][lane]

// ---------------- helpers ----------------
DEV_INLINE uint32_t smem_u32(const void* p) {
    uint32_t a;
    asm("{ .reg .u64 t; cvta.to.shared.u64 t, %1; cvt.u32.u64 %0, t; }"
        : "=r"(a) : "l"(p));
    return a;
}

DEV_INLINE uint32_t h2pack(float a, float b) {
    __half2 h = __floats2half2_rn(a, b);
    return *reinterpret_cast<uint32_t*>(&h);
}

DEV_INLINE void cp_async16(uint32_t dst_smem, const void* src) {
    asm volatile(
        "{\n\t.reg .u64 g;\n\tcvta.to.global.u64 g, %1;\n\t"
        "cp.async.cg.shared.global [%0], [g], 16;\n\t}"
        :: "r"(dst_smem), "l"(src));
}
DEV_INLINE void cp_commit() { asm volatile("cp.async.commit_group;"); }
template <int N> DEV_INLINE void cp_wait() {
    asm volatile("cp.async.wait_group %0;" :: "n"(N));
}

// m16n8k16 fp16 mma, fp32 accumulate
DEV_INLINE void mma_f16(float* c, const uint32_t* a, uint32_t b0, uint32_t b1) {
    asm volatile(
        "mma.sync.aligned.m16n8k16.row.col.f32.f16.f16.f32 "
        "{%0,%1,%2,%3}, {%4,%5,%6,%7}, {%8,%9}, {%0,%1,%2,%3};"
        : "+f"(c[0]), "+f"(c[1]), "+f"(c[2]), "+f"(c[3])
        : "r"(a[0]), "r"(a[1]), "r"(a[2]), "r"(a[3]), "r"(b0), "r"(b1));
}

DEV_INLINE float gelu_exact(float v) {
    return 0.5f * v * (1.0f + erff(v * 0.70710678118654752f));
}

// ---------------- kernel 1: fused single-read prep ----------------
// Blocks 0..511: (b, ft) slab -> LN stats + fp16 smem staging + B-frag pack.
// Blocks 512..639: pack W -> fp16 A-frag order.
__global__ __launch_bounds__(256) void prep_kernel(const float* __restrict__ x,
                                                   const float* __restrict__ gamma,
                                                   const float* __restrict__ beta,
                                                   const float* __restrict__ W) {
    const int tid = threadIdx.x;

    if (blockIdx.x >= 512) {                       // ---- pack W
        int lin = (blockIdx.x - 512) * 256 + tid;  // 32768 uint4s
        int lane = lin & 31;
        int kstep = (lin >> 5) & 1;
        int kc = (lin >> 6) & 15;
        int m16 = lin >> 10;
        int g = lane >> 2, tig = lane & 3;
        int mr = m16 * 16 + g;
        int tc = kc * 32 + kstep * 16 + 2 * tig;
        const float* w0 = W + (size_t)mr * T_ + tc;
        const float* w8 = W + (size_t)(mr + 8) * T_ + tc;
        uint4 v;
        v.x = h2pack(w0[0], w0[1]);
        v.y = h2pack(w8[0], w8[1]);
        v.z = h2pack(w0[8], w0[9]);
        v.w = h2pack(w8[8], w8[9]);
        g_WfragH[lin] = v;
        return;
    }

    extern __shared__ char dyn[];
    __half* sx   = reinterpret_cast<__half*>(dyn + OFF_SX);     // [512][136]
    float* s_red = reinterpret_cast<float*>(dyn + OFF_RED);     // [2][8][128]
    float* s_mu  = reinterpret_cast<float*>(dyn + OFF_MURS);
    float* s_rs  = s_mu + 128;
    float* s_g   = reinterpret_cast<float*>(dyn + OFF_GB);      // [512]
    float* s_b   = s_g + T_;

    const int b = blockIdx.x >> 2;
    const int ft = blockIdx.x & 3;

    // stage gamma/beta
#pragma unroll
    for (int r = 0; r < 2; r++) {
        int i = tid + r * 256;
        s_g[i] = gamma[i];
        s_b[i] = beta[i];
    }

    // ---- pass 1: single DRAM read; f32 stats + fp16 staging ----
    {
        const int fq = tid & 31;                   // float4 group (4 f's)
        const int tw = tid >> 5;                   // t block 0..7 (64 t each)
        float s0 = 0, s1 = 0, s2 = 0, s3 = 0;
        float q0 = 0, q1 = 0, q2 = 0, q3 = 0;
        const float* xp = x + ((size_t)b * T_ + tw * 64) * F_ + ft * 128 + fq * 4;
#pragma unroll 4
        for (int i = 0; i < 64; i++) {
            float4 v = *reinterpret_cast<const float4*>(xp + (size_t)i * F_);
            s0 += v.x; q0 += v.x * v.x;
            s1 += v.y; q1 += v.y * v.y;
            s2 += v.z; q2 += v.z * v.z;
            s3 += v.w; q3 += v.w * v.w;
            int t = tw * 64 + i;
            uint2 u;
            u.x = h2pack(v.x, v.y);
            u.y = h2pack(v.z, v.w);
            *reinterpret_cast<uint2*>(sx + t * SX_STRIDE + fq * 4) = u;
        }
        s_red[tw * 128 + fq * 4 + 0] = s0;
        s_red[tw * 128 + fq * 4 + 1] = s1;
        s_red[tw * 128 + fq * 4 + 2] = s2;
        s_red[tw * 128 + fq * 4 + 3] = s3;
        s_red[1024 + tw * 128 + fq * 4 + 0] = q0;
        s_red[1024 + tw * 128 + fq * 4 + 1] = q1;
        s_red[1024 + tw * 128 + fq * 4 + 2] = q2;
        s_red[1024 + tw * 128 + fq * 4 + 3] = q3;
    }
    __syncthreads();

    if (tid < 128) {
        float sm = 0.f, sq = 0.f;
#pragma unroll
        for (int w = 0; w < 8; w++) {
            sm += s_red[w * 128 + tid];
            sq += s_red[1024 + w * 128 + tid];
        }
        float mean = sm * (1.0f / T_);
        float var = sq * (1.0f / T_) - mean * mean;
        s_mu[tid] = mean;
        s_rs[tid] = rsqrtf(fmaxf(var, 0.0f) + LN_EPS);
    }
    __syncthreads();

    // ---- pass 2: normalize from smem (no DRAM re-read), write B-frags ----
    uint4* dst_base = g_BfragH + (((size_t)b * 4 + ft) * 16) * 512;
    for (int kc = 0; kc < 16; kc++) {
        uint4* dst = dst_base + (size_t)kc * 512;
#pragma unroll
        for (int r = 0; r < 2; r++) {
            int o = tid + r * 256;                 // 512 uint4s per kc
            int np = o >> 6;
            int rem = o & 63;
            int kstep = rem >> 5;
            int lane = rem & 31;
            int g = lane >> 2, tig = lane & 3;
            int t0 = kc * 32 + kstep * 16 + 2 * tig;
            int f0 = np * 16 + g;
            float mu0 = s_mu[f0], rs0 = s_rs[f0];
            float mu1 = s_mu[f0 + 8], rs1 = s_rs[f0 + 8];
            float ga0 = s_g[t0],     be0 = s_b[t0];
            float ga1 = s_g[t0 + 1], be1 = s_b[t0 + 1];
            float ga8 = s_g[t0 + 8], be8 = s_b[t0 + 8];
            float ga9 = s_g[t0 + 9], be9 = s_b[t0 + 9];
            const __half* c0 = sx + t0 * SX_STRIDE + f0;
            uint4 v;
            v.x = h2pack((__half2float(c0[0])              - mu0) * rs0 * ga0 + be0,
                         (__half2float(c0[SX_STRIDE])      - mu0) * rs0 * ga1 + be1);
            v.y = h2pack((__half2float(c0[8 * SX_STRIDE])  - mu0) * rs0 * ga8 + be8,
                         (__half2float(c0[9 * SX_STRIDE])  - mu0) * rs0 * ga9 + be9);
            v.z = h2pack((__half2float(c0[8])                  - mu1) * rs1 * ga0 + be0,
                         (__half2float(c0[SX_STRIDE + 8])      - mu1) * rs1 * ga1 + be1);
            v.w = h2pack((__half2float(c0[8 * SX_STRIDE + 8])  - mu1) * rs1 * ga8 + be8,
                         (__half2float(c0[9 * SX_STRIDE + 8])  - mu1) * rs1 * ga9 + be9);
            dst[o] = v;
        }
    }
}

// ---------------- kernel 2: fp16 GEMM (f32 acc) + bias + GELU + residual (R12) ------
// BK=64: smem A = [m16l (8)][ks (4)][lane], B = [np (8)][ks (4)][lane] (uint4 units)
__global__ __launch_bounds__(THREADS, 2)
void timemix_gemm_kernel(const float* __restrict__ x,
                         const float* __restrict__ bvec,
                         float* __restrict__ out) {
    extern __shared__ char smem[];
    const int tid = threadIdx.x;
    const int wid = tid >> 5, lane = tid & 31;
    const int wm = wid & 3, wn = wid >> 2;          // 4 x 2 warps (32m x 64f)
    const int bm = blockIdx.x;                      // 0..3
    const int ft = blockIdx.y;                      // 0..3
    const int b = blockIdx.z;

    const uint32_t smem_base = smem_u32(smem);
    const uint4* Bsrc_base = g_BfragH + (((size_t)b * 4 + ft) * 16) * 512;

    auto load_stage = [&](int kc8) {
        uint32_t sA = smem_base + (kc8 % NSTAGE) * STAGE_B;
        uint32_t sB = sA + A_STAGE_B;
#pragma unroll
        for (int r = 0; r < 4; r++) {               // A: 1024 uint4s
            int i = tid + r * 256;
            int m16l = i >> 7;
            int off = i & 127;                      // ks*32 + lane
            const uint4* src = g_WfragH + (((size_t)(bm * 8 + m16l) * 32) + kc8 * 4) * 32 + off;
            cp_async16(sA + i * 16, src);
        }
#pragma unroll
        for (int r = 0; r < 4; r++) {               // B: 1024 uint4s
            int i = tid + r * 256;
            int np = i >> 7;
            int rem = i & 127;
            int ks = rem >> 5;
            int ln = rem & 31;
            const uint4* src = Bsrc_base + (size_t)(2 * kc8 + (ks >> 1)) * 512
                               + np * 64 + (ks & 1) * 32 + ln;
            cp_async16(sB + i * 16, src);
        }
        cp_commit();
    };

    float acc[2][8][4];
#pragma unroll
    for (int i = 0; i < 2; i++)
#pragma unroll
        for (int j = 0; j < 8; j++)
#pragma unroll
            for (int r = 0; r < 4; r++) acc[i][j][r] = 0.0f;

    load_stage(0);
    load_stage(1);

    for (int kc = 0; kc < NKC; kc++) {
        if (kc + 1 < NKC) cp_wait<1>(); else cp_wait<0>();
        __syncthreads();

        const uint4* sA = reinterpret_cast<const uint4*>(smem + (kc % NSTAGE) * STAGE_B);
        const uint4* sB = reinterpret_cast<const uint4*>(
            smem + (kc % NSTAGE) * STAGE_B + A_STAGE_B);

#pragma unroll
        for (int kstep = 0; kstep < 4; kstep++) {
            uint32_t a[2][4];
#pragma unroll
            for (int i = 0; i < 2; i++) {
                uint4 v = sA[((wm * 2 + i) * 4 + kstep) * 32 + lane];
                a[i][0] = v.x; a[i][1] = v.y; a[i][2] = v.z; a[i][3] = v.w;
            }
            uint4 bf[4];
#pragma unroll
            for (int jp = 0; jp < 4; jp++)
                bf[jp] = sB[((wn * 4 + jp) * 4 + kstep) * 32 + lane];
#pragma unroll
            for (int i = 0; i < 2; i++)
#pragma unroll
                for (int jp = 0; jp < 4; jp++) {
                    mma_f16(acc[i][2 * jp + 0], a[i], bf[jp].x, bf[jp].y);
                    mma_f16(acc[i][2 * jp + 1], a[i], bf[jp].z, bf[jp].w);
                }
        }

        if (kc + 2 < NKC) load_stage(kc + 2);
    }

    // ---- epilogue: bias + exact GELU + residual ----
    const int g = lane >> 2, tig = lane & 3;
    const int m_warp = bm * 128 + wm * 32;
    const int f_warp = ft * 128 + wn * 64;
#pragma unroll
    for (int i = 0; i < 2; i++) {
#pragma unroll
        for (int h = 0; h < 2; h++) {
            int m = m_warp + i * 16 + g + 8 * h;
            float bv = bvec[m];
            const float* xr = x + ((size_t)b * M_ + m) * F_ + f_warp;
            float* yr = out + ((size_t)b * M_ + m) * F_ + f_warp;
#pragma unroll
            for (int j = 0; j < 8; j++) {
                int fo = j * 8 + tig * 2;
                float2 xv = *reinterpret_cast<const float2*>(xr + fo);
                float2 o;
                o.x = gelu_exact(acc[i][j][2 * h + 0] + bv) + xv.x;
                o.y = gelu_exact(acc[i][j][2 * h + 1] + bv) + xv.y;
                *reinterpret_cast<float2*>(yr + fo) = o;
            }
        }
    }
}

// ---------------- launch ----------------
extern "C" void kernel_launch(void* const* d_in, const int* in_sizes, int n_in,
                              void* d_out, int out_size) {
    const float* x     = (const float*)d_in[0];
    const float* gamma = (const float*)d_in[1];
    const float* beta  = (const float*)d_in[2];
    const float* W     = (const float*)d_in[3];
    const float* bvec  = (const float*)d_in[4];
    float* out = (float*)d_out;

    cudaFuncSetAttribute(prep_kernel,
                         cudaFuncAttributeMaxDynamicSharedMemorySize, PREP_SMEM);
    cudaFuncSetAttribute(timemix_gemm_kernel,
                         cudaFuncAttributeMaxDynamicSharedMemorySize, SMEM_BYTES);

    prep_kernel<<<512 + 128, 256, PREP_SMEM>>>(x, gamma, beta, W);
    {
        dim3 grid(M_ / BM, F_ / BN, B_);   // (4, 4, 128)
        timemix_gemm_kernel<<<grid, THREADS, SMEM_BYTES>>>(x, bvec, out);
    }
}

// round 15
// speedup vs baseline: 1.0047x; 1.0047x over previous
#include <cuda_runtime.h>
#include <cuda_fp16.h>
#include <cstdint>
#include <math.h>

#define DEV_INLINE __device__ __forceinline__

// Problem dims (fixed by the dataset)
constexpr int B_ = 128, T_ = 512, F_ = 512, M_ = 512;
constexpr float LN_EPS = 1e-5f;

// GEMM tiling (R12-verified 122.9us): CTA 128x128x64; 8 warps of 32x64; fp16 mma k16, f32 acc
constexpr int BM = 128, BN = 128, BK = 64;
constexpr int NKC = T_ / BK;     // 8 k-chunks
constexpr int THREADS = 256;
constexpr int NSTAGE = 3;

constexpr int A_STAGE_B = BM * BK * 2;            // 16384 B
constexpr int B_STAGE_B = BN * BK * 2;            // 16384 B
constexpr int STAGE_B   = A_STAGE_B + B_STAGE_B;  // 32 KB
constexpr int SMEM_BYTES = NSTAGE * STAGE_B;      // 96 KB

// Prep kernel dynamic smem layout (bytes)
constexpr int SX_STRIDE = 136;                     // halfs per row (8B-aligned rows)
constexpr int OFF_SX   = 0;                        // __half [512][136] = 139264
constexpr int OFF_RED  = 139264;                   // float [2][8][128] = 8192
constexpr int OFF_MURS = 147456;                   // float [2][128]   = 1024
constexpr int OFF_GB   = 148480;                   // float [2][512]   = 4096
constexpr int PREP_SMEM = 152576;

// Device scratch (no allocation allowed)
__device__ uint4 g_WfragH[32 * 16 * 2 * 32];           // 512KB: [m16][kc32][kstep2][lane]
__device__ uint4 g_BfragH[(size_t)B_ * 4 * 16 * 512];  // 64MB: [b][ft][kc32][np][kstep2][lane]

// ---------------- helpers ----------------
DEV_INLINE uint32_t smem_u32(const void* p) {
    uint32_t a;
    asm("{ .reg .u64 t; cvta.to.shared.u64 t, %1; cvt.u32.u64 %0, t; }"
        : "=r"(a) : "l"(p));
    return a;
}

DEV_INLINE uint32_t h2pack(float a, float b) {
    __half2 h = __floats2half2_rn(a, b);
    return *reinterpret_cast<uint32_t*>(&h);
}

DEV_INLINE void cp_async16(uint32_t dst_smem, const void* src) {
    asm volatile(
        "{\n\t.reg .u64 g;\n\tcvta.to.global.u64 g, %1;\n\t"
        "cp.async.cg.shared.global [%0], [g], 16;\n\t}"
        :: "r"(dst_smem), "l"(src));
}
DEV_INLINE void cp_commit() { asm volatile("cp.async.commit_group;"); }
template <int N> DEV_INLINE void cp_wait() {
    asm volatile("cp.async.wait_group %0;" :: "n"(N));
}

// m16n8k16 fp16 mma, fp32 accumulate
DEV_INLINE void mma_f16(float* c, const uint32_t* a, uint32_t b0, uint32_t b1) {
    asm volatile(
        "mma.sync.aligned.m16n8k16.row.col.f32.f16.f16.f32 "
        "{%0,%1,%2,%3}, {%4,%5,%6,%7}, {%8,%9}, {%0,%1,%2,%3};"
        : "+f"(c[0]), "+f"(c[1]), "+f"(c[2]), "+f"(c[3])
        : "r"(a[0]), "r"(a[1]), "r"(a[2]), "r"(a[3]), "r"(b0), "r"(b1));
}

DEV_INLINE float gelu_exact(float v) {
    return 0.5f * v * (1.0f + erff(v * 0.70710678118654752f));
}

// ---------------- kernel 1: fused single-read prep ----------------
// Blocks 0..511: (b, ft) slab -> LN stats + fp16 smem staging + B-frag pack.
// Blocks 512..639: pack W -> fp16 A-frag order.
__global__ __launch_bounds__(256) void prep_kernel(const float* __restrict__ x,
                                                   const float* __restrict__ gamma,
                                                   const float* __restrict__ beta,
                                                   const float* __restrict__ W) {
    const int tid = threadIdx.x;

    if (blockIdx.x >= 512) {                       // ---- pack W
        int lin = (blockIdx.x - 512) * 256 + tid;  // 32768 uint4s
        int lane = lin & 31;
        int kstep = (lin >> 5) & 1;
        int kc = (lin >> 6) & 15;
        int m16 = lin >> 10;
        int g = lane >> 2, tig = lane & 3;
        int mr = m16 * 16 + g;
        int tc = kc * 32 + kstep * 16 + 2 * tig;
        const float* w0 = W + (size_t)mr * T_ + tc;
        const float* w8 = W + (size_t)(mr + 8) * T_ + tc;
        uint4 v;
        v.x = h2pack(w0[0], w0[1]);
        v.y = h2pack(w8[0], w8[1]);
        v.z = h2pack(w0[8], w0[9]);
        v.w = h2pack(w8[8], w8[9]);
        g_WfragH[lin] = v;
        return;
    }

    extern __shared__ char dyn[];
    __half* sx   = reinterpret_cast<__half*>(dyn + OFF_SX);     // [512][136]
    float* s_red = reinterpret_cast<float*>(dyn + OFF_RED);     // [2][8][128]
    float* s_mu  = reinterpret_cast<float*>(dyn + OFF_MURS);
    float* s_rs  = s_mu + 128;
    float* s_g   = reinterpret_cast<float*>(dyn + OFF_GB);      // [512]
    float* s_b   = s_g + T_;

    const int b = blockIdx.x >> 2;
    const int ft = blockIdx.x & 3;

    // stage gamma/beta
#pragma unroll
    for (int r = 0; r < 2; r++) {
        int i = tid + r * 256;
        s_g[i] = gamma[i];
        s_b[i] = beta[i];
    }

    // ---- pass 1: single DRAM read; f32 stats + fp16 staging ----
    {
        const int fq = tid & 31;                   // float4 group (4 f's)
        const int tw = tid >> 5;                   // t block 0..7 (64 t each)
        float s0 = 0, s1 = 0, s2 = 0, s3 = 0;
        float q0 = 0, q1 = 0, q2 = 0, q3 = 0;
        const float* xp = x + ((size_t)b * T_ + tw * 64) * F_ + ft * 128 + fq * 4;
#pragma unroll 4
        for (int i = 0; i < 64; i++) {
            float4 v = *reinterpret_cast<const float4*>(xp + (size_t)i * F_);
            s0 += v.x; q0 += v.x * v.x;
            s1 += v.y; q1 += v.y * v.y;
            s2 += v.z; q2 += v.z * v.z;
            s3 += v.w; q3 += v.w * v.w;
            int t = tw * 64 + i;
            uint2 u;
            u.x = h2pack(v.x, v.y);
            u.y = h2pack(v.z, v.w);
            *reinterpret_cast<uint2*>(sx + t * SX_STRIDE + fq * 4) = u;
        }
        s_red[tw * 128 + fq * 4 + 0] = s0;
        s_red[tw * 128 + fq * 4 + 1] = s1;
        s_red[tw * 128 + fq * 4 + 2] = s2;
        s_red[tw * 128 + fq * 4 + 3] = s3;
        s_red[1024 + tw * 128 + fq * 4 + 0] = q0;
        s_red[1024 + tw * 128 + fq * 4 + 1] = q1;
        s_red[1024 + tw * 128 + fq * 4 + 2] = q2;
        s_red[1024 + tw * 128 + fq * 4 + 3] = q3;
    }
    __syncthreads();

    if (tid < 128) {
        float sm = 0.f, sq = 0.f;
#pragma unroll
        for (int w = 0; w < 8; w++) {
            sm += s_red[w * 128 + tid];
            sq += s_red[1024 + w * 128 + tid];
        }
        float mean = sm * (1.0f / T_);
        float var = sq * (1.0f / T_) - mean * mean;
        s_mu[tid] = mean;
        s_rs[tid] = rsqrtf(fmaxf(var, 0.0f) + LN_EPS);
    }
    __syncthreads();

    // ---- pass 2: normalize from smem (no DRAM re-read), write B-frags ----
    uint4* dst_base = g_BfragH + (((size_t)b * 4 + ft) * 16) * 512;
    for (int kc = 0; kc < 16; kc++) {
        uint4* dst = dst_base + (size_t)kc * 512;
#pragma unroll
        for (int r = 0; r < 2; r++) {
            int o = tid + r * 256;                 // 512 uint4s per kc
            int np = o >> 6;
            int rem = o & 63;
            int kstep = rem >> 5;
            int lane = rem & 31;
            int g = lane >> 2, tig = lane & 3;
            int t0 = kc * 32 + kstep * 16 + 2 * tig;
            int f0 = np * 16 + g;
            float mu0 = s_mu[f0], rs0 = s_rs[f0];
            float mu1 = s_mu[f0 + 8], rs1 = s_rs[f0 + 8];
            float ga0 = s_g[t0],     be0 = s_b[t0];
            float ga1 = s_g[t0 + 1], be1 = s_b[t0 + 1];
            float ga8 = s_g[t0 + 8], be8 = s_b[t0 + 8];
            float ga9 = s_g[t0 + 9], be9 = s_b[t0 + 9];
            const __half* c0 = sx + t0 * SX_STRIDE + f0;
            uint4 v;
            v.x = h2pack((__half2float(c0[0])              - mu0) * rs0 * ga0 + be0,
                         (__half2float(c0[SX_STRIDE])      - mu0) * rs0 * ga1 + be1);
            v.y = h2pack((__half2float(c0[8 * SX_STRIDE])  - mu0) * rs0 * ga8 + be8,
                         (__half2float(c0[9 * SX_STRIDE])  - mu0) * rs0 * ga9 + be9);
            v.z = h2pack((__half2float(c0[8])                  - mu1) * rs1 * ga0 + be0,
                         (__half2float(c0[SX_STRIDE + 8])      - mu1) * rs1 * ga1 + be1);
            v.w = h2pack((__half2float(c0[8 * SX_STRIDE + 8])  - mu1) * rs1 * ga8 + be8,
                         (__half2float(c0[9 * SX_STRIDE + 8])  - mu1) * rs1 * ga9 + be9);
            dst[o] = v;
        }
    }
}

// ---------------- kernel 2: fp16 GEMM (f32 acc) + bias + GELU + residual (R12) ------
// BK=64: smem A = [m16l (8)][ks (4)][lane], B = [np (8)][ks (4)][lane] (uint4 units)
__global__ __launch_bounds__(THREADS, 2)
void timemix_gemm_kernel(const float* __restrict__ x,
                         const float* __restrict__ bvec,
                         float* __restrict__ out) {
    extern __shared__ char smem[];
    const int tid = threadIdx.x;
    const int wid = tid >> 5, lane = tid & 31;
    const int wm = wid & 3, wn = wid >> 2;          // 4 x 2 warps (32m x 64f)
    const int bm = blockIdx.x;                      // 0..3
    const int ft = blockIdx.y;                      // 0..3
    const int b = blockIdx.z;

    const uint32_t smem_base = smem_u32(smem);
    const uint4* Bsrc_base = g_BfragH + (((size_t)b * 4 + ft) * 16) * 512;

    auto load_stage = [&](int kc8) {
        uint32_t sA = smem_base + (kc8 % NSTAGE) * STAGE_B;
        uint32_t sB = sA + A_STAGE_B;
#pragma unroll
        for (int r = 0; r < 4; r++) {               // A: 1024 uint4s
            int i = tid + r * 256;
            int m16l = i >> 7;
            int off = i & 127;                      // ks*32 + lane
            const uint4* src = g_WfragH + (((size_t)(bm * 8 + m16l) * 32) + kc8 * 4) * 32 + off;
            cp_async16(sA + i * 16, src);
        }
#pragma unroll
        for (int r = 0; r < 4; r++) {               // B: 1024 uint4s
            int i = tid + r * 256;
            int np = i >> 7;
            int rem = i & 127;
            int ks = rem >> 5;
            int ln = rem & 31;
            const uint4* src = Bsrc_base + (size_t)(2 * kc8 + (ks >> 1)) * 512
                               + np * 64 + (ks & 1) * 32 + ln;
            cp_async16(sB + i * 16, src);
        }
        cp_commit();
    };

    float acc[2][8][4];
#pragma unroll
    for (int i = 0; i < 2; i++)
#pragma unroll
        for (int j = 0; j < 8; j++)
#pragma unroll
            for (int r = 0; r < 4; r++) acc[i][j][r] = 0.0f;

    load_stage(0);
    load_stage(1);

    for (int kc = 0; kc < NKC; kc++) {
        if (kc + 1 < NKC) cp_wait<1>(); else cp_wait<0>();
        __syncthreads();

        const uint4* sA = reinterpret_cast<const uint4*>(smem + (kc % NSTAGE) * STAGE_B);
        const uint4* sB = reinterpret_cast<const uint4*>(
            smem + (kc % NSTAGE) * STAGE_B + A_STAGE_B);

#pragma unroll
        for (int kstep = 0; kstep < 4; kstep++) {
            uint32_t a[2][4];
#pragma unroll
            for (int i = 0; i < 2; i++) {
                uint4 v = sA[((wm * 2 + i) * 4 + kstep) * 32 + lane];
                a[i][0] = v.x; a[i][1] = v.y; a[i][2] = v.z; a[i][3] = v.w;
            }
            uint4 bf[4];
#pragma unroll
            for (int jp = 0; jp < 4; jp++)
                bf[jp] = sB[((wn * 4 + jp) * 4 + kstep) * 32 + lane];
#pragma unroll
            for (int i = 0; i < 2; i++)
#pragma unroll
                for (int jp = 0; jp < 4; jp++) {
                    mma_f16(acc[i][2 * jp + 0], a[i], bf[jp].x, bf[jp].y);
                    mma_f16(acc[i][2 * jp + 1], a[i], bf[jp].z, bf[jp].w);
                }
        }

        if (kc + 2 < NKC) load_stage(kc + 2);
    }

    // ---- epilogue: bias + exact GELU + residual ----
    const int g = lane >> 2, tig = lane & 3;
    const int m_warp = bm * 128 + wm * 32;
    const int f_warp = ft * 128 + wn * 64;
#pragma unroll
    for (int i = 0; i < 2; i++) {
#pragma unroll
        for (int h = 0; h < 2; h++) {
            int m = m_warp + i * 16 + g + 8 * h;
            float bv = bvec[m];
            const float* xr = x + ((size_t)b * M_ + m) * F_ + f_warp;
            float* yr = out + ((size_t)b * M_ + m) * F_ + f_warp;
#pragma unroll
            for (int j = 0; j < 8; j++) {
                int fo = j * 8 + tig * 2;
                float2 xv = *reinterpret_cast<const float2*>(xr + fo);
                float2 o;
                o.x = gelu_exact(acc[i][j][2 * h + 0] + bv) + xv.x;
                o.y = gelu_exact(acc[i][j][2 * h + 1] + bv) + xv.y;
                *reinterpret_cast<float2*>(yr + fo) = o;
            }
        }
    }
}

// ---------------- launch ----------------
extern "C" void kernel_launch(void* const* d_in, const int* in_sizes, int n_in,
                              void* d_out, int out_size) {
    const float* x     = (const float*)d_in[0];
    const float* gamma = (const float*)d_in[1];
    const float* beta  = (const float*)d_in[2];
    const float* W     = (const float*)d_in[3];
    const float* bvec  = (const float*)d_in[4];
    float* out = (float*)d_out;

    cudaFuncSetAttribute(prep_kernel,
                         cudaFuncAttributeMaxDynamicSharedMemorySize, PREP_SMEM);
    cudaFuncSetAttribute(timemix_gemm_kernel,
                         cudaFuncAttributeMaxDynamicSharedMemorySize, SMEM_BYTES);

    prep_kernel<<<512 + 128, 256, PREP_SMEM>>>(x, gamma, beta, W);
    {
        dim3 grid(M_ / BM, F_ / BN, B_);   // (4, 4, 128)
        timemix_gemm_kernel<<<grid, THREADS, SMEM_BYTES>>>(x, bvec, out);
    }
}